// round 4
// baseline (speedup 1.0000x reference)
#include <cuda_runtime.h>

// RLGate: B=4, T=2048, D=1024, E=8, K=2
// Inputs: x[B,T,D] f32, expert_outputs[E,B,T,D] f32, rewards[B,T] f32,
//         W[D,E] f32, b[E] f32, baseline[] f32, noise_u[B,T,E] f32, top_k i32
// Output: final_output[B,T,D] f32 + aux_loss scalar at index B*T*D

#define BB      4
#define TT      2048
#define DD      1024
#define EE      8
#define NTOK    (BB * TT)          // 8192
#define TPB_TOK 8                   // tokens per CTA
#define NCTA    (NTOK / TPB_TOK)    // 1024
#define EPSF    1e-9f

__global__ void rlgate_zero_aux(float* __restrict__ out) {
    out[(size_t)NTOK * DD] = 0.0f;
}

__global__ __launch_bounds__(256) void rlgate_kernel(
    const float* __restrict__ x,
    const float* __restrict__ eo,
    const float* __restrict__ rewards,
    const float* __restrict__ W,
    const float* __restrict__ bias,
    const float* __restrict__ baseline,
    const float* __restrict__ noise_u,
    float* __restrict__ out)
{
    const int tid  = threadIdx.x;
    const int lane = tid & 31;
    const int warp = tid >> 5;
    const int tokBase = blockIdx.x * TPB_TOK;

    __shared__ __align__(16) float Wt[EE][1032];        // transposed W, padded rows
    __shared__ float part[TPB_TOK][64];                 // per-warp expert partials
    __shared__ float logit_s[TPB_TOK][EE];
    __shared__ int   sidx_s[TPB_TOK][2];

    // ---- Phase 0: stage W -> smem transposed (coalesced gmem) ----
    const float4* W4 = reinterpret_cast<const float4*>(W);   // 2048 float4
    #pragma unroll
    for (int k = 0; k < 8; k++) {
        int idx = tid + 256 * k;          // float4 index
        float4 wv = W4[idx];
        int d  = idx >> 1;
        int e0 = (idx & 1) * 4;
        Wt[e0 + 0][d] = wv.x;
        Wt[e0 + 1][d] = wv.y;
        Wt[e0 + 2][d] = wv.z;
        Wt[e0 + 3][d] = wv.w;
    }
    __syncthreads();

    // hoist this thread's W slice (d = 4*tid..4*tid+3, all 8 experts) to regs.
    float wr[EE][4];
    #pragma unroll
    for (int e = 0; e < EE; e++) {
        float4 t4 = *reinterpret_cast<const float4*>(&Wt[e][4 * tid]);
        wr[e][0] = t4.x; wr[e][1] = t4.y; wr[e][2] = t4.z; wr[e][3] = t4.w;
    }

    // ---- Phase 1: logits partials, all 8 tokens; x loads front-batched ----
    const float4* X4 = reinterpret_cast<const float4*>(x);
    float4 xv[TPB_TOK];
    #pragma unroll
    for (int t = 0; t < TPB_TOK; t++)
        xv[t] = X4[(size_t)(tokBase + t) * (DD / 4) + tid];

    #pragma unroll
    for (int t = 0; t < TPB_TOK; t++) {
        float v[EE];
        #pragma unroll
        for (int e = 0; e < EE; e++) {
            v[e] = xv[t].x * wr[e][0];
            v[e] = fmaf(xv[t].y, wr[e][1], v[e]);
            v[e] = fmaf(xv[t].z, wr[e][2], v[e]);
            v[e] = fmaf(xv[t].w, wr[e][3], v[e]);
        }
        // 16-shuffle multi-value warp reduction (split after each round)
        #pragma unroll
        for (int e = 0; e < EE; e++) v[e] += __shfl_xor_sync(0xFFFFFFFFu, v[e], 16);
        if (lane & 16) { v[0] = v[4]; v[1] = v[5]; v[2] = v[6]; v[3] = v[7]; }
        #pragma unroll
        for (int i = 0; i < 4; i++)  v[i] += __shfl_xor_sync(0xFFFFFFFFu, v[i], 8);
        if (lane & 8)  { v[0] = v[2]; v[1] = v[3]; }
        #pragma unroll
        for (int i = 0; i < 2; i++)  v[i] += __shfl_xor_sync(0xFFFFFFFFu, v[i], 4);
        if (lane & 4)  { v[0] = v[1]; }
        v[0] += __shfl_xor_sync(0xFFFFFFFFu, v[0], 2);
        v[0] += __shfl_xor_sync(0xFFFFFFFFu, v[0], 1);
        // lane 4*e now holds the warp sum for expert e
        if ((lane & 3) == 0) part[t][warp * 8 + (lane >> 2)] = v[0];
    }
    __syncthreads();

    // ---- Phase 2a: cross-warp sum -> logits (64 threads) ----
    if (tid < TPB_TOK * EE) {
        const int t = tid >> 3, e = tid & 7;
        float s = bias[e];
        #pragma unroll
        for (int w = 0; w < 8; w++) s += part[t][w * 8 + e];
        logit_s[t][e] = s;
    }
    __syncthreads();

    // ---- Phase 2b: softmax + gumbel top-2 + aux (8 threads, parallel) ----
    float contrib = 0.0f;
    if (tid < TPB_TOK) {
        const int t = tid;
        const int tok = tokBase + t;
        float l[EE];
        #pragma unroll
        for (int e = 0; e < EE; e++) l[e] = logit_s[t][e];
        float mx = l[0];
        #pragma unroll
        for (int e = 1; e < EE; e++) mx = fmaxf(mx, l[e]);
        float p[EE], sum = 0.0f;
        #pragma unroll
        for (int e = 0; e < EE; e++) { p[e] = __expf(l[e] - mx); sum += p[e]; }
        const float inv = 1.0f / sum;

        float lp[EE], sc[EE];
        const float* nu = noise_u + (size_t)tok * EE;
        #pragma unroll
        for (int e = 0; e < EE; e++) {
            lp[e] = logf(p[e] * inv + EPSF);
            float u = nu[e] * (1.0f - 2e-7f) + 1e-7f;
            sc[e] = lp[e] - logf(-logf(u));       // log_prob + gumbel
        }
        int i0 = 0;
        #pragma unroll
        for (int e = 1; e < EE; e++) if (sc[e] > sc[i0]) i0 = e;
        int i1 = (i0 == 0) ? 1 : 0;
        #pragma unroll
        for (int e = 0; e < EE; e++) if (e != i0 && sc[e] > sc[i1]) i1 = e;

        sidx_s[t][0] = i0;
        sidx_s[t][1] = i1;

        const float adv = rewards[tok] - baseline[0];
        contrib = -(adv * (lp[i0] + lp[i1])) * (1.0f / (float)NTOK);
    }
    if (tid < 32) {
        #pragma unroll
        for (int off = 4; off > 0; off >>= 1)
            contrib += __shfl_down_sync(0xFFFFFFFFu, contrib, off);
        if (lane == 0) atomicAdd(out + (size_t)NTOK * DD, contrib);
    }
    __syncthreads();

    // ---- Phase 3: gather 2 expert rows per token, average, write ----
    const float4* EO4 = reinterpret_cast<const float4*>(eo);
    float4* OUT4 = reinterpret_cast<float4*>(out);
    #pragma unroll
    for (int tb = 0; tb < TPB_TOK; tb += 4) {
        float4 a[4], c[4];
        #pragma unroll
        for (int j = 0; j < 4; j++) {
            const int tok = tokBase + tb + j;
            const size_t base4 = (size_t)tok * (DD / 4) + tid;
            a[j] = EO4[(size_t)sidx_s[tb + j][0] * NTOK * (DD / 4) + base4];
            c[j] = EO4[(size_t)sidx_s[tb + j][1] * NTOK * (DD / 4) + base4];
        }
        #pragma unroll
        for (int j = 0; j < 4; j++) {
            const int tok = tokBase + tb + j;
            const size_t base4 = (size_t)tok * (DD / 4) + tid;
            float4 r;
            r.x = (a[j].x + c[j].x) * 0.5f;
            r.y = (a[j].y + c[j].y) * 0.5f;
            r.z = (a[j].z + c[j].z) * 0.5f;
            r.w = (a[j].w + c[j].w) * 0.5f;
            OUT4[base4] = r;
        }
    }
}

extern "C" void kernel_launch(void* const* d_in, const int* in_sizes, int n_in,
                              void* d_out, int out_size) {
    const float* x        = (const float*)d_in[0];
    const float* eo       = (const float*)d_in[1];
    const float* rewards  = (const float*)d_in[2];
    const float* W        = (const float*)d_in[3];
    const float* bias     = (const float*)d_in[4];
    const float* baseline = (const float*)d_in[5];
    const float* noise_u  = (const float*)d_in[6];
    float* out = (float*)d_out;

    rlgate_zero_aux<<<1, 1>>>(out);
    rlgate_kernel<<<NCTA, 256>>>(x, eo, rewards, W, bias, baseline, noise_u, out);
}